// round 1
// baseline (speedup 1.0000x reference)
#include <cuda_runtime.h>
#include <cuda_bf16.h>

#define NB    8
#define NPTS  8192
#define E     128
#define HG    64
#define WG    64
#define SG    (HG*WG)          // 4096
#define NCELL (NB*SG)          // 32768
#define NPT   (NB*NPTS)        // 65536
#define MAXP  20
#define NH    8

// ---------------- scratch (device globals; no allocation allowed) ----------------
__device__ int   g_count[NCELL];
__device__ int   g_slots[NCELL*MAXP];
__device__ float g_A[E*NH];                    // folded score matrix, k-major [k][h]
__device__ float g_score[NPT*NH];              // per-point per-head scores
__device__ float g_gscore[NCELL*NH];           // grid-token scores
__device__ float g_V[(size_t)NPT*E];           // z @ Wv
__device__ float g_gV[(size_t)NCELL*E];        // z_grid @ Wv
__device__ float g_attout[(size_t)NCELL*E];    // attention output (pre-Wo)

// ---------------- kernels ----------------
__global__ void zero_kernel() {
    int i = blockIdx.x*blockDim.x + threadIdx.x;
    if (i < NCELL) g_count[i] = 0;
}

// q = latent @ Wq ; A[k][h] = 0.25 * sum_{i<16} Wk[k][16h+i] * q[16h+i]
__global__ void prep_kernel(const float* __restrict__ latent,
                            const float* __restrict__ Wq,
                            const float* __restrict__ Wk) {
    __shared__ float q[E];
    __shared__ float lat[E];
    int t = threadIdx.x;            // 128 threads
    lat[t] = latent[t];
    __syncthreads();
    float a = 0.f;
    #pragma unroll 8
    for (int d = 0; d < E; d++) a += lat[d] * Wq[d*E + t];
    q[t] = a;
    __syncthreads();
    #pragma unroll
    for (int h = 0; h < NH; h++) {
        float s = 0.f;
        #pragma unroll
        for (int i = 0; i < 16; i++) s += Wk[t*E + h*16 + i] * q[h*16 + i];
        g_A[t*NH + h] = s * 0.25f;   // fold 1/sqrt(dh)=1/4
    }
}

__global__ void scatter_kernel(const float* __restrict__ x) {
    int p = blockIdx.x*blockDim.x + threadIdx.x;
    if (p >= NPT) return;
    int b = p >> 13;                 // p / 8192
    float x0 = x[2*p], x1 = x[2*p+1];
    int i0 = (int)rintf(x0 * 63.0f); i0 = min(max(i0, 0), 63);  // round-half-even == jnp.round
    int i1 = (int)rintf(x1 * 63.0f); i1 = min(max(i1, 0), 63);
    int cell = b*SG + i0*WG + i1;
    int slot = atomicAdd(&g_count[cell], 1);
    if (slot < MAXP) g_slots[cell*MAXP + slot] = p;
}

// Sout[p*8+h] = sum_k Z[p][k] * A[k][h]
__global__ void score_kernel(const float* __restrict__ Z, float* __restrict__ Sout, int M) {
    __shared__ float As[E*NH];
    int t = threadIdx.x;             // 256
    ((float4*)As)[t] = ((const float4*)g_A)[t];   // 1024 floats
    __syncthreads();
    int id = blockIdx.x*256 + t;
    int p = id >> 3, h = id & 7;
    if (p >= M) return;
    const float4* zr = (const float4*)(Z + (size_t)p*E);
    float a = 0.f;
    #pragma unroll 8
    for (int k4 = 0; k4 < 32; k4++) {
        float4 v = zr[k4];
        int k = k4*4;
        a += v.x*As[(k+0)*NH+h] + v.y*As[(k+1)*NH+h]
           + v.z*As[(k+2)*NH+h] + v.w*As[(k+3)*NH+h];
    }
    Sout[id] = a;
}

// C[M x 128] = Z[M x 128] @ W[128 x 128], tile 64 rows/block, 256 threads, 8x4 microtile
#define GEMM_SMEM_FLOATS (E*E + E*65)
__global__ void gemm128_kernel(const float* __restrict__ Z,
                               const float* __restrict__ W,
                               float* __restrict__ C) {
    extern __shared__ float sm[];
    float* Ws = sm;            // [128][128]
    float* Zs = sm + E*E;      // [128][65]  (transposed tile, pad 65 -> warp broadcast reads)
    int t = threadIdx.x;       // 256

    {   // load W (once per block)
        const float4* W4 = (const float4*)W;
        float4* Ws4 = (float4*)Ws;
        #pragma unroll
        for (int i = 0; i < 16; i++) Ws4[t + 256*i] = W4[t + 256*i];
    }
    int m0 = blockIdx.x * 64;
    #pragma unroll
    for (int i = 0; i < 8; i++) {   // load Z tile transposed
        int fid = t + 256*i;
        int r = fid >> 5;
        int k = (fid & 31) << 2;
        float4 v = *(const float4*)(Z + (size_t)(m0 + r)*E + k);
        Zs[(k+0)*65 + r] = v.x;
        Zs[(k+1)*65 + r] = v.y;
        Zs[(k+2)*65 + r] = v.z;
        Zs[(k+3)*65 + r] = v.w;
    }
    __syncthreads();

    int tx = t & 31;           // col group: cols tx*4 .. tx*4+3
    int ty = t >> 5;           // row group: rows ty*8 .. ty*8+7
    float acc[8][4];
    #pragma unroll
    for (int r = 0; r < 8; r++)
        #pragma unroll
        for (int c = 0; c < 4; c++) acc[r][c] = 0.f;

    const int colbase = tx*4;
    #pragma unroll 4
    for (int k = 0; k < E; k++) {
        float4 w = *(float4*)(Ws + k*E + colbase);
        float zr[8];
        #pragma unroll
        for (int r = 0; r < 8; r++) zr[r] = Zs[k*65 + ty*8 + r];  // warp-broadcast
        #pragma unroll
        for (int r = 0; r < 8; r++) {
            acc[r][0] += zr[r]*w.x;
            acc[r][1] += zr[r]*w.y;
            acc[r][2] += zr[r]*w.z;
            acc[r][3] += zr[r]*w.w;
        }
    }
    #pragma unroll
    for (int r = 0; r < 8; r++) {
        float4 o = make_float4(acc[r][0], acc[r][1], acc[r][2], acc[r][3]);
        *(float4*)(C + (size_t)(m0 + ty*8 + r)*E + colbase) = o;
    }
}

// one warp per cell: softmax over <=21 tokens per head, weighted sum of V rows
__global__ void attn_kernel(const float* __restrict__ V,   const float* __restrict__ Ssc,
                            const float* __restrict__ gV,  const float* __restrict__ gS,
                            float* __restrict__ out) {
    __shared__ int toks[8][MAXP];
    int warp = threadIdx.x >> 5, lane = threadIdx.x & 31;
    int g = blockIdx.x*8 + warp;     // cell id
    int cnt = g_count[g];
    int kk = min(cnt, MAXP);
    if (lane < kk) toks[warp][lane] = g_slots[g*MAXP + lane];
    __syncwarp();

    int h = lane >> 2;               // head for this lane's 4 output dims
    // pass 1: max
    float m = gS[g*NH + h];
    for (int tkn = 0; tkn < kk; tkn++) {
        int p = toks[warp][tkn];
        m = fmaxf(m, Ssc[p*NH + h]);
    }
    // pass 2: accumulate exp-weighted sum
    float e = expf(gS[g*NH + h] - m);
    float sum = e;
    float4 gv = *(const float4*)(gV + (size_t)g*E + lane*4);
    float4 acc = make_float4(e*gv.x, e*gv.y, e*gv.z, e*gv.w);
    for (int tkn = 0; tkn < kk; tkn++) {
        int p = toks[warp][tkn];
        float w = expf(Ssc[p*NH + h] - m);
        sum += w;
        float4 v = *(const float4*)(V + (size_t)p*E + lane*4);
        acc.x += w*v.x; acc.y += w*v.y; acc.z += w*v.z; acc.w += w*v.w;
    }
    float inv = 1.0f / sum;
    float4 o = make_float4(acc.x*inv, acc.y*inv, acc.z*inv, acc.w*inv);
    *(float4*)(out + (size_t)g*E + lane*4) = o;
}

// ---------------- launch ----------------
extern "C" void kernel_launch(void* const* d_in, const int* in_sizes, int n_in,
                              void* d_out, int out_size) {
    const float* x      = (const float*)d_in[0];
    const float* z      = (const float*)d_in[1];
    const float* x_grid = (const float*)d_in[2];
    const float* z_grid = (const float*)d_in[3];
    const float* latent = (const float*)d_in[4];
    const float* Wq     = (const float*)d_in[5];
    const float* Wk     = (const float*)d_in[6];
    const float* Wv     = (const float*)d_in[7];
    const float* Wo     = (const float*)d_in[8];

    float* out = (float*)d_out;
    float* zg_out = out;
    const int XG_ELEMS = NB*SG*2;                 // 65536
    if (out_size == NCELL*E + XG_ELEMS) {         // tuple (x_grid, zg) concatenated
        cudaMemcpyAsync(out, x_grid, (size_t)XG_ELEMS*sizeof(float),
                        cudaMemcpyDeviceToDevice);
        zg_out = out + XG_ELEMS;
    }

    void *pV, *pgV, *pS, *pgS, *pAO;
    cudaGetSymbolAddress(&pV,  g_V);
    cudaGetSymbolAddress(&pgV, g_gV);
    cudaGetSymbolAddress(&pS,  g_score);
    cudaGetSymbolAddress(&pgS, g_gscore);
    cudaGetSymbolAddress(&pAO, g_attout);

    const int smem = GEMM_SMEM_FLOATS * sizeof(float);   // ~98.8 KB
    cudaFuncSetAttribute(gemm128_kernel, cudaFuncAttributeMaxDynamicSharedMemorySize, smem);

    zero_kernel<<<(NCELL+255)/256, 256>>>();
    prep_kernel<<<1, 128>>>(latent, Wq, Wk);
    scatter_kernel<<<(NPT+255)/256, 256>>>(x);

    gemm128_kernel<<<NPT/64,   256, smem>>>(z,      Wv, (float*)pV);
    gemm128_kernel<<<NCELL/64, 256, smem>>>(z_grid, Wv, (float*)pgV);
    score_kernel<<<(NPT*NH)/256,   256>>>(z,      (float*)pS,  NPT);
    score_kernel<<<(NCELL*NH)/256, 256>>>(z_grid, (float*)pgS, NCELL);

    attn_kernel<<<NCELL/8, 256>>>((const float*)pV, (const float*)pS,
                                  (const float*)pgV, (const float*)pgS, (float*)pAO);

    gemm128_kernel<<<NCELL/64, 256, smem>>>((const float*)pAO, Wo, zg_out);
}

// round 3
// speedup vs baseline: 1.3290x; 1.3290x over previous
#include <cuda_runtime.h>
#include <cuda_bf16.h>
#include <cstdint>

#define NB    8
#define NPTS  8192
#define E     128
#define HG    64
#define WG    64
#define SG    (HG*WG)          // 4096
#define NCELL (NB*SG)          // 32768
#define NPT   (NB*NPTS)        // 65536
#define MAXP  20
#define NH    8

// ---------------- scratch ----------------
__device__ int   g_count[NCELL];
__device__ int   g_slots[NCELL*MAXP];
__device__ float g_A[E*NH];
__device__ float g_score[NPT*NH];
__device__ float g_gscore[NCELL*NH];
__device__ float g_V[(size_t)NPT*E];
__device__ float g_gV[(size_t)NCELL*E];
__device__ float g_attout[(size_t)NCELL*E];

// ---------------- tensor-core GEMM via mma.sync (sm_80 baseline PTX) ----------------
// C[M x 128] = Z[M x 128] @ W[128 x 128], fp32 in/out.
// bf16 hi/lo split, 3 accumulating passes (AhBh + AlBh + AhBl) -> ~1.5e-5 rel error.
// Block: 128 rows x 128 cols, 256 threads = 8 warps in 4(m) x 2(n) grid,
// each warp 32x64 = 2x8 m16n8k16 tiles, fp32 register accumulators.

#define SK 136                          // bf16 row stride (pad: bank-conflict-free frags)
#define TILE_BYTES (128*SK*2)           // 34816 B per array
#define GEMM_SMEM  (4*TILE_BYTES)       // Ahi, Alo, Bhi, Blo = 139264 B

__device__ __forceinline__ void mma16816(float* c, uint32_t a0, uint32_t a1, uint32_t a2,
                                         uint32_t a3, uint32_t b0, uint32_t b1) {
    asm volatile(
        "mma.sync.aligned.m16n8k16.row.col.f32.bf16.bf16.f32 "
        "{%0,%1,%2,%3}, {%4,%5,%6,%7}, {%8,%9}, {%0,%1,%2,%3};"
        : "+f"(c[0]), "+f"(c[1]), "+f"(c[2]), "+f"(c[3])
        : "r"(a0), "r"(a1), "r"(a2), "r"(a3), "r"(b0), "r"(b1));
}

__device__ __forceinline__ uint32_t pack_hi(float x, float y) {
    __nv_bfloat162 h = __halves2bfloat162(__float2bfloat16(x), __float2bfloat16(y));
    return *(uint32_t*)&h;
}
__device__ __forceinline__ uint32_t pack_lo(float x, float y) {
    __nv_bfloat16 hx = __float2bfloat16(x), hy = __float2bfloat16(y);
    __nv_bfloat162 l = __halves2bfloat162(__float2bfloat16(x - __bfloat162float(hx)),
                                          __float2bfloat16(y - __bfloat162float(hy)));
    return *(uint32_t*)&l;
}

__global__ void __launch_bounds__(256) gemm_tc(const float* __restrict__ Z,
                                               const float* __restrict__ W,
                                               float* __restrict__ C) {
    extern __shared__ __nv_bfloat16 sm[];
    __nv_bfloat16* Ahi = sm;                    // [128][SK] row-major (m, k)
    __nv_bfloat16* Alo = sm + 128*SK;
    __nv_bfloat16* Bhi = sm + 2*128*SK;         // [128][SK] (n, k)  == W^T
    __nv_bfloat16* Blo = sm + 3*128*SK;

    const int t    = threadIdx.x;
    const int wid  = t >> 5;
    const int lane = t & 31;
    const int m0   = blockIdx.x * 128;

    // ---- load + split Z tile: each thread one half-row (64 floats) ----
    {
        int row = t >> 1;
        int kh  = (t & 1) << 6;
        const float4* zr = (const float4*)(Z + (size_t)(m0 + row) * E + kh);
        __nv_bfloat16* ah = Ahi + row*SK + kh;
        __nv_bfloat16* al = Alo + row*SK + kh;
        #pragma unroll
        for (int i = 0; i < 16; i++) {
            float4 v = zr[i];
            ((uint32_t*)(ah + i*4))[0] = pack_hi(v.x, v.y);
            ((uint32_t*)(ah + i*4))[1] = pack_hi(v.z, v.w);
            ((uint32_t*)(al + i*4))[0] = pack_lo(v.x, v.y);
            ((uint32_t*)(al + i*4))[1] = pack_lo(v.z, v.w);
        }
    }
    // ---- load + split + transpose W -> Bs[n][k] ----
    #pragma unroll
    for (int it = 0; it < 16; it++) {
        int id = it * 256 + t;          // 4096 = 128 k * 32 n-groups
        int k  = id >> 5;
        int n0 = (id & 31) << 2;
        float4 v = *(const float4*)(W + (size_t)k * E + n0);
        float vv[4] = {v.x, v.y, v.z, v.w};
        #pragma unroll
        for (int j = 0; j < 4; j++) {
            __nv_bfloat16 h = __float2bfloat16(vv[j]);
            Bhi[(n0 + j)*SK + k] = h;
            Blo[(n0 + j)*SK + k] = __float2bfloat16(vv[j] - __bfloat162float(h));
        }
    }
    __syncthreads();

    const int mw = wid >> 1;            // 0..3 : rows mw*32
    const int nw = wid & 1;             // 0..1 : cols nw*64
    const int g  = lane >> 2;           // group id
    const int tg = lane & 3;            // thread-in-group

    float acc[2][8][4];
    #pragma unroll
    for (int a = 0; a < 2; a++)
        #pragma unroll
        for (int b = 0; b < 8; b++)
            #pragma unroll
            for (int c = 0; c < 4; c++) acc[a][b][c] = 0.f;

    const __nv_bfloat16* Asel[3] = {Ahi, Alo, Ahi};
    const __nv_bfloat16* Bsel[3] = {Bhi, Bhi, Blo};

    #pragma unroll
    for (int p = 0; p < 3; p++) {
        const __nv_bfloat16* As = Asel[p];
        const __nv_bfloat16* Bs = Bsel[p];
        #pragma unroll
        for (int ks = 0; ks < 8; ks++) {
            const int k0 = ks * 16;
            uint32_t af[2][4];
            #pragma unroll
            for (int mt = 0; mt < 2; mt++) {
                const __nv_bfloat16* base = As + (mw*32 + mt*16 + g)*SK + k0 + tg*2;
                af[mt][0] = *(const uint32_t*)(base);
                af[mt][1] = *(const uint32_t*)(base + 8*SK);
                af[mt][2] = *(const uint32_t*)(base + 8);
                af[mt][3] = *(const uint32_t*)(base + 8*SK + 8);
            }
            uint32_t bf[8][2];
            #pragma unroll
            for (int nt = 0; nt < 8; nt++) {
                const __nv_bfloat16* base = Bs + (nw*64 + nt*8 + g)*SK + k0 + tg*2;
                bf[nt][0] = *(const uint32_t*)(base);
                bf[nt][1] = *(const uint32_t*)(base + 8);
            }
            #pragma unroll
            for (int mt = 0; mt < 2; mt++)
                #pragma unroll
                for (int nt = 0; nt < 8; nt++)
                    mma16816(acc[mt][nt], af[mt][0], af[mt][1], af[mt][2], af[mt][3],
                             bf[nt][0], bf[nt][1]);
        }
    }

    // ---- epilogue: fp32 stores ----
    #pragma unroll
    for (int mt = 0; mt < 2; mt++) {
        int row = m0 + mw*32 + mt*16 + g;
        #pragma unroll
        for (int nt = 0; nt < 8; nt++) {
            int col = nw*64 + nt*8 + tg*2;
            *(float2*)(C + (size_t)row * E + col) =
                make_float2(acc[mt][nt][0], acc[mt][nt][1]);
            *(float2*)(C + (size_t)(row + 8) * E + col) =
                make_float2(acc[mt][nt][2], acc[mt][nt][3]);
        }
    }
}

// ---------------- non-GEMM kernels ----------------
__global__ void zero_kernel() {
    int i = blockIdx.x * blockDim.x + threadIdx.x;
    if (i < NCELL) g_count[i] = 0;
}

__global__ void prep_kernel(const float* __restrict__ latent,
                            const float* __restrict__ Wq,
                            const float* __restrict__ Wk) {
    __shared__ float q[E];
    __shared__ float lat[E];
    int t = threadIdx.x;
    lat[t] = latent[t];
    __syncthreads();
    float a = 0.f;
    #pragma unroll 8
    for (int d = 0; d < E; d++) a += lat[d] * Wq[d*E + t];
    q[t] = a;
    __syncthreads();
    #pragma unroll
    for (int h = 0; h < NH; h++) {
        float s = 0.f;
        #pragma unroll
        for (int i = 0; i < 16; i++) s += Wk[t*E + h*16 + i] * q[h*16 + i];
        g_A[t*NH + h] = s * 0.25f;
    }
}

__global__ void scatter_kernel(const float* __restrict__ x) {
    int p = blockIdx.x * blockDim.x + threadIdx.x;
    if (p >= NPT) return;
    int b = p >> 13;
    float x0 = x[2*p], x1 = x[2*p+1];
    int i0 = (int)rintf(x0 * 63.0f); i0 = min(max(i0, 0), 63);
    int i1 = (int)rintf(x1 * 63.0f); i1 = min(max(i1, 0), 63);
    int cell = b*SG + i0*WG + i1;
    int slot = atomicAdd(&g_count[cell], 1);
    if (slot < MAXP) g_slots[cell*MAXP + slot] = p;
}

__global__ void score_kernel(const float* __restrict__ Z, float* __restrict__ Sout, int M) {
    __shared__ float As[E*NH];
    int t = threadIdx.x;
    ((float4*)As)[t] = ((const float4*)g_A)[t];
    __syncthreads();
    int id = blockIdx.x*256 + t;
    int p = id >> 3, h = id & 7;
    if (p >= M) return;
    const float4* zr = (const float4*)(Z + (size_t)p*E);
    float a = 0.f;
    #pragma unroll 8
    for (int k4 = 0; k4 < 32; k4++) {
        float4 v = zr[k4];
        int k = k4*4;
        a += v.x*As[(k+0)*NH+h] + v.y*As[(k+1)*NH+h]
           + v.z*As[(k+2)*NH+h] + v.w*As[(k+3)*NH+h];
    }
    Sout[id] = a;
}

__global__ void attn_kernel(const float* __restrict__ V,   const float* __restrict__ Ssc,
                            const float* __restrict__ gV,  const float* __restrict__ gS,
                            float* __restrict__ out) {
    __shared__ int toks[8][MAXP];
    int warp = threadIdx.x >> 5, lane = threadIdx.x & 31;
    int g = blockIdx.x*8 + warp;
    int cnt = g_count[g];
    int kk = min(cnt, MAXP);
    if (lane < kk) toks[warp][lane] = g_slots[g*MAXP + lane];
    __syncwarp();

    int h = lane >> 2;
    float m = gS[g*NH + h];
    for (int tkn = 0; tkn < kk; tkn++) {
        int p = toks[warp][tkn];
        m = fmaxf(m, Ssc[p*NH + h]);
    }
    float e = expf(gS[g*NH + h] - m);
    float sum = e;
    float4 gv = *(const float4*)(gV + (size_t)g*E + lane*4);
    float4 acc = make_float4(e*gv.x, e*gv.y, e*gv.z, e*gv.w);
    for (int tkn = 0; tkn < kk; tkn++) {
        int p = toks[warp][tkn];
        float w = expf(Ssc[p*NH + h] - m);
        sum += w;
        float4 v = *(const float4*)(V + (size_t)p*E + lane*4);
        acc.x += w*v.x; acc.y += w*v.y; acc.z += w*v.z; acc.w += w*v.w;
    }
    float inv = 1.0f / sum;
    float4 o = make_float4(acc.x*inv, acc.y*inv, acc.z*inv, acc.w*inv);
    *(float4*)(out + (size_t)g*E + lane*4) = o;
}

// ---------------- launch ----------------
extern "C" void kernel_launch(void* const* d_in, const int* in_sizes, int n_in,
                              void* d_out, int out_size) {
    const float* x      = (const float*)d_in[0];
    const float* z      = (const float*)d_in[1];
    const float* x_grid = (const float*)d_in[2];
    const float* z_grid = (const float*)d_in[3];
    const float* latent = (const float*)d_in[4];
    const float* Wq     = (const float*)d_in[5];
    const float* Wk     = (const float*)d_in[6];
    const float* Wv     = (const float*)d_in[7];
    const float* Wo     = (const float*)d_in[8];

    float* out = (float*)d_out;
    float* zg_out = out;
    const int XG_ELEMS = NB*SG*2;
    if (out_size == NCELL*E + XG_ELEMS) {
        cudaMemcpyAsync(out, x_grid, (size_t)XG_ELEMS*sizeof(float),
                        cudaMemcpyDeviceToDevice);
        zg_out = out + XG_ELEMS;
    }

    void *pV, *pgV, *pS, *pgS, *pAO;
    cudaGetSymbolAddress(&pV,  g_V);
    cudaGetSymbolAddress(&pgV, g_gV);
    cudaGetSymbolAddress(&pS,  g_score);
    cudaGetSymbolAddress(&pgS, g_gscore);
    cudaGetSymbolAddress(&pAO, g_attout);

    cudaFuncSetAttribute(gemm_tc, cudaFuncAttributeMaxDynamicSharedMemorySize, GEMM_SMEM);

    zero_kernel<<<(NCELL+255)/256, 256>>>();
    prep_kernel<<<1, 128>>>(latent, Wq, Wk);
    scatter_kernel<<<(NPT+255)/256, 256>>>(x);

    gemm_tc<<<NPT/128,   256, GEMM_SMEM>>>(z,      Wv, (float*)pV);
    gemm_tc<<<NCELL/128, 256, GEMM_SMEM>>>(z_grid, Wv, (float*)pgV);
    score_kernel<<<(NPT*NH)/256,   256>>>(z,      (float*)pS,  NPT);
    score_kernel<<<(NCELL*NH)/256, 256>>>(z_grid, (float*)pgS, NCELL);

    attn_kernel<<<NCELL/8, 256>>>((const float*)pV, (const float*)pS,
                                  (const float*)pgV, (const float*)pgS, (float*)pAO);

    gemm_tc<<<NCELL/128, 256, GEMM_SMEM>>>((const float*)pAO, Wo, zg_out);
}

// round 6
// speedup vs baseline: 1.5645x; 1.1772x over previous
#include <cuda_runtime.h>
#include <cuda_bf16.h>
#include <cstdint>

#define NB    8
#define NPTS  8192
#define E     128
#define HG    64
#define WG    64
#define SG    (HG*WG)          // 4096
#define NCELL (NB*SG)          // 32768
#define NPT   (NB*NPTS)        // 65536
#define NROWS (NPT+NCELL)      // 98304
#define MAXP  20
#define NH    8

// ---------------- scratch ----------------
__device__ int   g_count[NCELL];
__device__ int   g_slots[NCELL*MAXP];
__device__ __nv_bfloat16 g_ATh[NH*E];          // folded score matrix, [h][k], bf16 hi
__device__ __nv_bfloat16 g_ATl[NH*E];          // bf16 lo residual
__device__ float g_score[(size_t)NROWS*NH];    // point scores then grid scores
__device__ float g_V[(size_t)NROWS*E];         // z@Wv then z_grid@Wv
__device__ float g_attout[(size_t)NCELL*E];

// ---------------- mma / ldmatrix helpers ----------------
__device__ __forceinline__ void mma16816(float* c, const uint32_t* a, uint32_t b0, uint32_t b1) {
    asm volatile(
        "mma.sync.aligned.m16n8k16.row.col.f32.bf16.bf16.f32 "
        "{%0,%1,%2,%3}, {%4,%5,%6,%7}, {%8,%9}, {%0,%1,%2,%3};"
        : "+f"(c[0]), "+f"(c[1]), "+f"(c[2]), "+f"(c[3])
        : "r"(a[0]), "r"(a[1]), "r"(a[2]), "r"(a[3]), "r"(b0), "r"(b1));
}
__device__ __forceinline__ void ldsm_x4(uint32_t* r, uint32_t a) {
    asm volatile("ldmatrix.sync.aligned.m8n8.x4.shared.b16 {%0,%1,%2,%3}, [%4];"
        : "=r"(r[0]), "=r"(r[1]), "=r"(r[2]), "=r"(r[3]) : "r"(a));
}
__device__ __forceinline__ void ldsm_x2(uint32_t* r, uint32_t a) {
    asm volatile("ldmatrix.sync.aligned.m8n8.x2.shared.b16 {%0,%1}, [%2];"
        : "=r"(r[0]), "=r"(r[1]) : "r"(a));
}
__device__ __forceinline__ uint32_t pack_hi(float x, float y) {
    __nv_bfloat162 h = __halves2bfloat162(__float2bfloat16(x), __float2bfloat16(y));
    return *(uint32_t*)&h;
}
__device__ __forceinline__ uint32_t pack_lo(float x, float y) {
    __nv_bfloat16 hx = __float2bfloat16(x), hy = __float2bfloat16(y);
    __nv_bfloat162 l = __halves2bfloat162(__float2bfloat16(x - __bfloat162float(hx)),
                                          __float2bfloat16(y - __bfloat162float(hy)));
    return *(uint32_t*)&l;
}

// ---------------- fused GEMM (+ optional score) ----------------
// C[row, 0:128] = Zsrc[row] @ W ; Sout[row, 0:8] = Zsrc[row] @ AT^T
// bf16 hi/lo split, 3 accumulating passes. 128x128 tile, 256 thr = 8 warps (4m x 2n).
#define SK 136
#define SM_AHI 0
#define SM_ALO (128*SK)
#define SM_BHI (256*SK)
#define SM_BLO (384*SK)
#define SM_SBH (512*SK)
#define SM_SBL (520*SK)
#define GEMM_SMEM (528*SK*2)     // 143616 B

template<bool DO_SCORE>
__global__ void __launch_bounds__(256) gemm_tc(const float* __restrict__ Z1,
                                               const float* __restrict__ Z2, int nb1,
                                               const float* __restrict__ W,
                                               float* __restrict__ C,
                                               float* __restrict__ Sout) {
    extern __shared__ __nv_bfloat16 sm[];
    const int t    = threadIdx.x;
    const int wid  = t >> 5;
    const int lane = t & 31;
    const int gRow0 = blockIdx.x * 128;                 // global (output) row base
    const float* src;
    int m0;                                             // source row base
    if ((int)blockIdx.x < nb1) { src = Z1; m0 = gRow0; }
    else                       { src = Z2; m0 = (blockIdx.x - nb1) * 128; }

    // ---- stage + split Z tile: each thread one half-row (64 floats) ----
    {
        int row = t >> 1;
        int kh  = (t & 1) << 6;
        const float4* zr = (const float4*)(src + (size_t)(m0 + row) * E + kh);
        __nv_bfloat16* ah = sm + SM_AHI + row*SK + kh;
        __nv_bfloat16* al = sm + SM_ALO + row*SK + kh;
        #pragma unroll
        for (int i = 0; i < 16; i++) {
            float4 v = zr[i];
            ((uint32_t*)(ah + i*4))[0] = pack_hi(v.x, v.y);
            ((uint32_t*)(ah + i*4))[1] = pack_hi(v.z, v.w);
            ((uint32_t*)(al + i*4))[0] = pack_lo(v.x, v.y);
            ((uint32_t*)(al + i*4))[1] = pack_lo(v.z, v.w);
        }
    }
    // ---- stage + split + transpose W -> Bs[n][k] ----
    #pragma unroll
    for (int it = 0; it < 16; it++) {
        int id = it * 256 + t;
        int k  = id >> 5;
        int n0 = (id & 31) << 2;
        float4 v = *(const float4*)(W + (size_t)k * E + n0);
        float vv[4] = {v.x, v.y, v.z, v.w};
        #pragma unroll
        for (int j = 0; j < 4; j++) {
            __nv_bfloat16 h = __float2bfloat16(vv[j]);
            sm[SM_BHI + (n0 + j)*SK + k] = h;
            sm[SM_BLO + (n0 + j)*SK + k] = __float2bfloat16(vv[j] - __bfloat162float(h));
        }
    }
    if (DO_SCORE) {     // stage score matrix AT[8][128] hi/lo
        for (int idx = t; idx < NH*E; idx += 256) {
            int h = idx >> 7, k = idx & 127;
            sm[SM_SBH + h*SK + k] = g_ATh[idx];
            sm[SM_SBL + h*SK + k] = g_ATl[idx];
        }
    }
    __syncthreads();

    const int mw = wid >> 1;            // 0..3
    const int nw = wid & 1;             // 0..1
    const int g  = lane >> 2;
    const int tg = lane & 3;

    const uint32_t sb = (uint32_t)__cvta_generic_to_shared(sm);

    // per-lane ldmatrix addresses (byte offsets in smem)
    uint32_t aAh[2], aAl[2];
    #pragma unroll
    for (int mt = 0; mt < 2; mt++) {
        int row = mw*32 + mt*16 + (lane & 15);
        int col = (lane >> 4) << 3;
        aAh[mt] = sb + (SM_AHI + row*SK + col) * 2;
        aAl[mt] = sb + (SM_ALO + row*SK + col) * 2;
    }
    uint32_t aBh[4], aBl[4];
    #pragma unroll
    for (int c = 0; c < 4; c++) {
        int row = nw*64 + c*16 + (lane & 7) + ((lane >> 4) << 3);
        int col = ((lane >> 3) & 1) << 3;
        aBh[c] = sb + (SM_BHI + row*SK + col) * 2;
        aBl[c] = sb + (SM_BLO + row*SK + col) * 2;
    }
    uint32_t aSh = 0, aSl = 0;
    if (DO_SCORE) {
        int row = lane & 7;
        int col = ((lane >> 3) & 1) << 3;
        aSh = sb + (SM_SBH + row*SK + col) * 2;
        aSl = sb + (SM_SBL + row*SK + col) * 2;
    }

    float acc[2][8][4];
    #pragma unroll
    for (int a = 0; a < 2; a++)
        #pragma unroll
        for (int b = 0; b < 8; b++)
            #pragma unroll
            for (int c = 0; c < 4; c++) acc[a][b][c] = 0.f;
    float sacc[2][4] = {{0.f,0.f,0.f,0.f},{0.f,0.f,0.f,0.f}};

    #pragma unroll
    for (int ks = 0; ks < 8; ks++) {
        const uint32_t ko = ks * 32;    // 16 bf16 = 32 bytes per kstep
        uint32_t ah[2][4], al[2][4];
        ldsm_x4(ah[0], aAh[0] + ko);
        ldsm_x4(ah[1], aAh[1] + ko);
        ldsm_x4(al[0], aAl[0] + ko);
        ldsm_x4(al[1], aAl[1] + ko);

        if (DO_SCORE && nw == 0) {
            uint32_t sh[2], sl[2];
            ldsm_x2(sh, aSh + ko);
            ldsm_x2(sl, aSl + ko);
            #pragma unroll
            for (int mt = 0; mt < 2; mt++) {
                mma16816(sacc[mt], ah[mt], sh[0], sh[1]);
                mma16816(sacc[mt], al[mt], sh[0], sh[1]);
                mma16816(sacc[mt], ah[mt], sl[0], sl[1]);
            }
        }
        #pragma unroll
        for (int c = 0; c < 4; c++) {
            uint32_t bh[4], bl[4];
            ldsm_x4(bh, aBh[c] + ko);
            ldsm_x4(bl, aBl[c] + ko);
            #pragma unroll
            for (int mt = 0; mt < 2; mt++) {
                mma16816(acc[mt][2*c+0], ah[mt], bh[0], bh[1]);
                mma16816(acc[mt][2*c+1], ah[mt], bh[2], bh[3]);
                mma16816(acc[mt][2*c+0], al[mt], bh[0], bh[1]);
                mma16816(acc[mt][2*c+1], al[mt], bh[2], bh[3]);
                mma16816(acc[mt][2*c+0], ah[mt], bl[0], bl[1]);
                mma16816(acc[mt][2*c+1], ah[mt], bl[2], bl[3]);
            }
        }
    }

    // ---- epilogue ----
    #pragma unroll
    for (int mt = 0; mt < 2; mt++) {
        int row = gRow0 + mw*32 + mt*16 + g;
        #pragma unroll
        for (int nt = 0; nt < 8; nt++) {
            int col = nw*64 + nt*8 + tg*2;
            *(float2*)(C + (size_t)row * E + col) =
                make_float2(acc[mt][nt][0], acc[mt][nt][1]);
            *(float2*)(C + (size_t)(row + 8) * E + col) =
                make_float2(acc[mt][nt][2], acc[mt][nt][3]);
        }
    }
    if (DO_SCORE && nw == 0) {
        #pragma unroll
        for (int mt = 0; mt < 2; mt++) {
            int row = gRow0 + mw*32 + mt*16 + g;
            *(float2*)(Sout + (size_t)row * NH + tg*2) =
                make_float2(sacc[mt][0], sacc[mt][1]);
            *(float2*)(Sout + (size_t)(row + 8) * NH + tg*2) =
                make_float2(sacc[mt][2], sacc[mt][3]);
        }
    }
}

// ---------------- non-GEMM kernels ----------------
__global__ void zero_kernel() {
    int i = blockIdx.x * blockDim.x + threadIdx.x;
    if (i < NCELL) g_count[i] = 0;
}

// q = latent @ Wq ; AT[h][k] = 0.25 * sum_i Wk[k][16h+i] * q[16h+i], split to bf16 hi/lo
__global__ void prep_kernel(const float* __restrict__ latent,
                            const float* __restrict__ Wq,
                            const float* __restrict__ Wk) {
    __shared__ float q[E];
    __shared__ float lat[E];
    int t = threadIdx.x;            // 128 threads
    lat[t] = latent[t];
    __syncthreads();
    float a = 0.f;
    #pragma unroll 8
    for (int d = 0; d < E; d++) a += lat[d] * Wq[d*E + t];
    q[t] = a;
    __syncthreads();
    #pragma unroll
    for (int h = 0; h < NH; h++) {
        float s = 0.f;
        #pragma unroll
        for (int i = 0; i < 16; i++) s += Wk[t*E + h*16 + i] * q[h*16 + i];
        s *= 0.25f;
        __nv_bfloat16 hi = __float2bfloat16(s);
        g_ATh[h*E + t] = hi;
        g_ATl[h*E + t] = __float2bfloat16(s - __bfloat162float(hi));
    }
}

__global__ void scatter_kernel(const float* __restrict__ x) {
    int p = blockIdx.x * blockDim.x + threadIdx.x;
    if (p >= NPT) return;
    int b = p >> 13;
    float x0 = x[2*p], x1 = x[2*p+1];
    int i0 = (int)rintf(x0 * 63.0f); i0 = min(max(i0, 0), 63);
    int i1 = (int)rintf(x1 * 63.0f); i1 = min(max(i1, 0), 63);
    int cell = b*SG + i0*WG + i1;
    int slot = atomicAdd(&g_count[cell], 1);
    if (slot < MAXP) g_slots[cell*MAXP + slot] = p;
}

__global__ void attn_kernel() {
    const float* V   = g_V;                      // point rows
    const float* gV  = g_V + (size_t)NPT*E;      // grid rows
    const float* Ssc = g_score;
    const float* gS  = g_score + (size_t)NPT*NH;
    float* out = g_attout;

    __shared__ int toks[8][MAXP];
    int warp = threadIdx.x >> 5, lane = threadIdx.x & 31;
    int g = blockIdx.x*8 + warp;
    int cnt = g_count[g];
    int kk = min(cnt, MAXP);
    if (lane < kk) toks[warp][lane] = g_slots[g*MAXP + lane];
    __syncwarp();

    int h = lane >> 2;
    float m = gS[g*NH + h];
    for (int tkn = 0; tkn < kk; tkn++) {
        int p = toks[warp][tkn];
        m = fmaxf(m, Ssc[p*NH + h]);
    }
    float e = expf(gS[g*NH + h] - m);
    float sum = e;
    float4 gv = *(const float4*)(gV + (size_t)g*E + lane*4);
    float4 acc = make_float4(e*gv.x, e*gv.y, e*gv.z, e*gv.w);
    for (int tkn = 0; tkn < kk; tkn++) {
        int p = toks[warp][tkn];
        float w = expf(Ssc[p*NH + h] - m);
        sum += w;
        float4 v = *(const float4*)(V + (size_t)p*E + lane*4);
        acc.x += w*v.x; acc.y += w*v.y; acc.z += w*v.z; acc.w += w*v.w;
    }
    float inv = 1.0f / sum;
    float4 o = make_float4(acc.x*inv, acc.y*inv, acc.z*inv, acc.w*inv);
    *(float4*)(out + (size_t)g*E + lane*4) = o;
}

// ---------------- launch ----------------
extern "C" void kernel_launch(void* const* d_in, const int* in_sizes, int n_in,
                              void* d_out, int out_size) {
    const float* x      = (const float*)d_in[0];
    const float* z      = (const float*)d_in[1];
    const float* x_grid = (const float*)d_in[2];
    const float* z_grid = (const float*)d_in[3];
    const float* latent = (const float*)d_in[4];
    const float* Wq     = (const float*)d_in[5];
    const float* Wk     = (const float*)d_in[6];
    const float* Wv     = (const float*)d_in[7];
    const float* Wo     = (const float*)d_in[8];

    float* out = (float*)d_out;
    float* zg_out = out;
    const int XG_ELEMS = NB*SG*2;
    if (out_size == NCELL*E + XG_ELEMS) {
        cudaMemcpyAsync(out, x_grid, (size_t)XG_ELEMS*sizeof(float),
                        cudaMemcpyDeviceToDevice);
        zg_out = out + XG_ELEMS;
    }

    void *pV, *pS, *pAO;
    cudaGetSymbolAddress(&pV,  g_V);
    cudaGetSymbolAddress(&pS,  g_score);
    cudaGetSymbolAddress(&pAO, g_attout);

    cudaFuncSetAttribute(gemm_tc<true>,  cudaFuncAttributeMaxDynamicSharedMemorySize, GEMM_SMEM);
    cudaFuncSetAttribute(gemm_tc<false>, cudaFuncAttributeMaxDynamicSharedMemorySize, GEMM_SMEM);

    zero_kernel<<<(NCELL+255)/256, 256>>>();
    prep_kernel<<<1, 128>>>(latent, Wq, Wk);
    scatter_kernel<<<(NPT+255)/256, 256>>>(x);

    // fused: V/gV + scores in one launch (768 blocks)
    gemm_tc<true><<<NROWS/128, 256, GEMM_SMEM>>>(z, z_grid, NPT/128, Wv,
                                                 (float*)pV, (float*)pS);
    attn_kernel<<<NCELL/8, 256>>>();

    gemm_tc<false><<<NCELL/128, 256, GEMM_SMEM>>>((const float*)pAO, (const float*)pAO,
                                                  NCELL/128, Wo, zg_out, nullptr);
}

// round 7
// speedup vs baseline: 2.5734x; 1.6449x over previous
#include <cuda_runtime.h>
#include <cuda_bf16.h>
#include <cstdint>

#define NB    8
#define NPTS  8192
#define E     128
#define HG    64
#define WG    64
#define SG    (HG*WG)          // 4096
#define NCELL (NB*SG)          // 32768
#define NPT   (NB*NPTS)        // 65536
#define NROWS (NPT+NCELL)      // 98304
#define MAXP  20
#define NH    8

#define SK 136                 // padded k-stride (bf16 elements)

// ---------------- scratch ----------------
__device__ int   g_count[NCELL];
__device__ int   g_slots[NCELL*MAXP];
__device__ float g_score[(size_t)NROWS*NH];    // point scores then grid scores
__device__ float g_V[(size_t)NROWS*E];         // z@Wv then z_grid@Wv
__device__ float g_attout[(size_t)NCELL*E];
// pre-split weights: [Whi 128xSK][Wlo 128xSK][ATh 8xSK][ATl 8xSK]
__device__ __align__(16) __nv_bfloat16 g_WvSp[272*SK];
__device__ __align__(16) __nv_bfloat16 g_WoSp[256*SK];

// ---------------- mma / ldmatrix helpers ----------------
__device__ __forceinline__ void mma16816(float* c, const uint32_t* a, uint32_t b0, uint32_t b1) {
    asm volatile(
        "mma.sync.aligned.m16n8k16.row.col.f32.bf16.bf16.f32 "
        "{%0,%1,%2,%3}, {%4,%5,%6,%7}, {%8,%9}, {%0,%1,%2,%3};"
        : "+f"(c[0]), "+f"(c[1]), "+f"(c[2]), "+f"(c[3])
        : "r"(a[0]), "r"(a[1]), "r"(a[2]), "r"(a[3]), "r"(b0), "r"(b1));
}
__device__ __forceinline__ void ldsm_x4(uint32_t* r, uint32_t a) {
    asm volatile("ldmatrix.sync.aligned.m8n8.x4.shared.b16 {%0,%1,%2,%3}, [%4];"
        : "=r"(r[0]), "=r"(r[1]), "=r"(r[2]), "=r"(r[3]) : "r"(a));
}
__device__ __forceinline__ void ldsm_x2(uint32_t* r, uint32_t a) {
    asm volatile("ldmatrix.sync.aligned.m8n8.x2.shared.b16 {%0,%1}, [%2];"
        : "=r"(r[0]), "=r"(r[1]) : "r"(a));
}
__device__ __forceinline__ uint32_t pack_hi(float x, float y) {
    __nv_bfloat162 h = __halves2bfloat162(__float2bfloat16(x), __float2bfloat16(y));
    return *(uint32_t*)&h;
}
__device__ __forceinline__ uint32_t pack_lo(float x, float y) {
    __nv_bfloat16 hx = __float2bfloat16(x), hy = __float2bfloat16(y);
    __nv_bfloat162 l = __halves2bfloat162(__float2bfloat16(x - __bfloat162float(hx)),
                                          __float2bfloat16(y - __bfloat162float(hy)));
    return *(uint32_t*)&l;
}
__device__ __forceinline__ void cp_async16(uint32_t dst, const void* src) {
    asm volatile("cp.async.cg.shared.global [%0], [%1], 16;" :: "r"(dst), "l"(src));
}

// ---------------- fused GEMM (+ optional score) ----------------
// 64x128 tile, 256 thr = 8 warps (2m x 4n); each warp 32x32 = 2x4 m16n8 tiles.
// bf16 hi/lo split, 3 accumulating passes. 2 CTAs/SM.
#define SM_AHI 0
#define SM_ALO (64*SK)
#define SM_BHI (128*SK)
#define SM_BLO (256*SK)
#define SM_SBH (384*SK)
#define SM_SBL (392*SK)
#define GEMM_SMEM (400*SK*2)     // 108800 B

template<bool DO_SCORE>
__global__ void __launch_bounds__(256, 2) gemm_tc(const float* __restrict__ Z1,
                                                  const float* __restrict__ Z2, int nb1,
                                                  const __nv_bfloat16* __restrict__ Wsp,
                                                  int wbytes,
                                                  float* __restrict__ C,
                                                  float* __restrict__ Sout) {
    extern __shared__ __nv_bfloat16 sm[];
    const int t    = threadIdx.x;
    const int wid  = t >> 5;
    const int lane = t & 31;
    const int gRow0 = blockIdx.x * 64;
    const float* src;
    int m0;
    if ((int)blockIdx.x < nb1) { src = Z1; m0 = gRow0; }
    else                       { src = Z2; m0 = (blockIdx.x - nb1) * 64; }

    const uint32_t sb = (uint32_t)__cvta_generic_to_shared(sm);

    // ---- B (+score) staging: linear cp.async copy of pre-split blob ----
    {
        const char* gsrc = (const char*)Wsp;
        uint32_t bdst = sb + SM_BHI*2;
        for (int off = t*16; off < wbytes; off += 256*16)
            cp_async16(bdst + off, gsrc + off);
        asm volatile("cp.async.commit_group;");
    }

    // ---- A staging: each thread one quarter-row (32 floats), split hi/lo ----
    {
        int row = t >> 2;
        int kq  = (t & 3) << 5;
        const float4* zr = (const float4*)(src + (size_t)(m0 + row) * E + kq);
        __nv_bfloat16* ah = sm + SM_AHI + row*SK + kq;
        __nv_bfloat16* al = sm + SM_ALO + row*SK + kq;
        #pragma unroll
        for (int i = 0; i < 8; i++) {
            float4 v = zr[i];
            ((uint32_t*)(ah + i*4))[0] = pack_hi(v.x, v.y);
            ((uint32_t*)(ah + i*4))[1] = pack_hi(v.z, v.w);
            ((uint32_t*)(al + i*4))[0] = pack_lo(v.x, v.y);
            ((uint32_t*)(al + i*4))[1] = pack_lo(v.z, v.w);
        }
    }
    asm volatile("cp.async.wait_group 0;" ::: "memory");
    __syncthreads();

    const int mw = wid >> 2;            // 0..1 : rows mw*32
    const int nw = wid & 3;             // 0..3 : cols nw*32
    const int g  = lane >> 2;
    const int tg = lane & 3;

    // per-lane ldmatrix addresses (byte offsets)
    uint32_t aAh[2], aAl[2];
    #pragma unroll
    for (int mt = 0; mt < 2; mt++) {
        int row = mw*32 + mt*16 + (lane & 15);
        int col = (lane >> 4) << 3;
        aAh[mt] = sb + (SM_AHI + row*SK + col) * 2;
        aAl[mt] = sb + (SM_ALO + row*SK + col) * 2;
    }
    uint32_t aBh[2], aBl[2];
    #pragma unroll
    for (int c = 0; c < 2; c++) {
        int row = nw*32 + c*16 + (lane & 7) + ((lane >> 4) << 3);
        int col = ((lane >> 3) & 1) << 3;
        aBh[c] = sb + (SM_BHI + row*SK + col) * 2;
        aBl[c] = sb + (SM_BLO + row*SK + col) * 2;
    }
    uint32_t aSh = 0, aSl = 0;
    if (DO_SCORE) {
        int row = lane & 7;
        int col = ((lane >> 3) & 1) << 3;
        aSh = sb + (SM_SBH + row*SK + col) * 2;
        aSl = sb + (SM_SBL + row*SK + col) * 2;
    }

    float acc[2][4][4];
    #pragma unroll
    for (int a = 0; a < 2; a++)
        #pragma unroll
        for (int b = 0; b < 4; b++)
            #pragma unroll
            for (int c = 0; c < 4; c++) acc[a][b][c] = 0.f;
    float sacc[2][4] = {{0.f,0.f,0.f,0.f},{0.f,0.f,0.f,0.f}};

    #pragma unroll
    for (int ks = 0; ks < 8; ks++) {
        const uint32_t ko = ks * 32;
        uint32_t ah[2][4], al[2][4];
        ldsm_x4(ah[0], aAh[0] + ko);
        ldsm_x4(ah[1], aAh[1] + ko);
        ldsm_x4(al[0], aAl[0] + ko);
        ldsm_x4(al[1], aAl[1] + ko);

        if (DO_SCORE && nw == 0) {
            uint32_t sh[2], sl[2];
            ldsm_x2(sh, aSh + ko);
            ldsm_x2(sl, aSl + ko);
            #pragma unroll
            for (int mt = 0; mt < 2; mt++) {
                mma16816(sacc[mt], ah[mt], sh[0], sh[1]);
                mma16816(sacc[mt], al[mt], sh[0], sh[1]);
                mma16816(sacc[mt], ah[mt], sl[0], sl[1]);
            }
        }
        #pragma unroll
        for (int c = 0; c < 2; c++) {
            uint32_t bh[4], bl[4];
            ldsm_x4(bh, aBh[c] + ko);
            ldsm_x4(bl, aBl[c] + ko);
            #pragma unroll
            for (int mt = 0; mt < 2; mt++) {
                mma16816(acc[mt][2*c+0], ah[mt], bh[0], bh[1]);
                mma16816(acc[mt][2*c+1], ah[mt], bh[2], bh[3]);
                mma16816(acc[mt][2*c+0], al[mt], bh[0], bh[1]);
                mma16816(acc[mt][2*c+1], al[mt], bh[2], bh[3]);
                mma16816(acc[mt][2*c+0], ah[mt], bl[0], bl[1]);
                mma16816(acc[mt][2*c+1], ah[mt], bl[2], bl[3]);
            }
        }
    }

    // ---- epilogue ----
    #pragma unroll
    for (int mt = 0; mt < 2; mt++) {
        int row = gRow0 + mw*32 + mt*16 + g;
        #pragma unroll
        for (int nt = 0; nt < 4; nt++) {
            int col = nw*32 + nt*8 + tg*2;
            *(float2*)(C + (size_t)row * E + col) =
                make_float2(acc[mt][nt][0], acc[mt][nt][1]);
            *(float2*)(C + (size_t)(row + 8) * E + col) =
                make_float2(acc[mt][nt][2], acc[mt][nt][3]);
        }
    }
    if (DO_SCORE && nw == 0) {
        #pragma unroll
        for (int mt = 0; mt < 2; mt++) {
            int row = gRow0 + mw*32 + mt*16 + g;
            *(float2*)(Sout + (size_t)row * NH + tg*2) =
                make_float2(sacc[mt][0], sacc[mt][1]);
            *(float2*)(Sout + (size_t)(row + 8) * NH + tg*2) =
                make_float2(sacc[mt][2], sacc[mt][3]);
        }
    }
}

// ---------------- prep kernels ----------------
// split + transpose W -> dst = [hi 128xSK][lo 128xSK] (dst[n][k] = W[k][n])
__global__ void prep_w(const float* __restrict__ W, __nv_bfloat16* __restrict__ dst) {
    int n = blockIdx.x;     // 128
    int k = threadIdx.x;    // 128
    float v = W[(size_t)k*E + n];
    __nv_bfloat16 h = __float2bfloat16(v);
    dst[n*SK + k] = h;
    dst[128*SK + n*SK + k] = __float2bfloat16(v - __bfloat162float(h));
}

// q = latent @ Wq ; AT[h][k] = 0.25 * sum_i Wk[k][16h+i] * q[16h+i] -> appended to g_WvSp
__global__ void prep_kernel(const float* __restrict__ latent,
                            const float* __restrict__ Wq,
                            const float* __restrict__ Wk) {
    __shared__ float q[E];
    __shared__ float lat[E];
    int t = threadIdx.x;            // 128 threads
    lat[t] = latent[t];
    __syncthreads();
    float a = 0.f;
    #pragma unroll 8
    for (int d = 0; d < E; d++) a += lat[d] * Wq[d*E + t];
    q[t] = a;
    __syncthreads();
    #pragma unroll
    for (int h = 0; h < NH; h++) {
        float s = 0.f;
        #pragma unroll
        for (int i = 0; i < 16; i++) s += Wk[t*E + h*16 + i] * q[h*16 + i];
        s *= 0.25f;
        __nv_bfloat16 hi = __float2bfloat16(s);
        g_WvSp[256*SK + h*SK + t] = hi;
        g_WvSp[264*SK + h*SK + t] = __float2bfloat16(s - __bfloat162float(hi));
    }
}

__global__ void zero_kernel() {
    int i = blockIdx.x * blockDim.x + threadIdx.x;
    if (i < NCELL) g_count[i] = 0;
}

__global__ void scatter_kernel(const float* __restrict__ x) {
    int p = blockIdx.x * blockDim.x + threadIdx.x;
    if (p >= NPT) return;
    int b = p >> 13;
    float x0 = x[2*p], x1 = x[2*p+1];
    int i0 = (int)rintf(x0 * 63.0f); i0 = min(max(i0, 0), 63);
    int i1 = (int)rintf(x1 * 63.0f); i1 = min(max(i1, 0), 63);
    int cell = b*SG + i0*WG + i1;
    int slot = atomicAdd(&g_count[cell], 1);
    if (slot < MAXP) g_slots[cell*MAXP + slot] = p;
}

__global__ void attn_kernel() {
    const float* V   = g_V;
    const float* gV  = g_V + (size_t)NPT*E;
    const float* Ssc = g_score;
    const float* gS  = g_score + (size_t)NPT*NH;
    float* out = g_attout;

    __shared__ int toks[8][MAXP];
    int warp = threadIdx.x >> 5, lane = threadIdx.x & 31;
    int g = blockIdx.x*8 + warp;
    int cnt = g_count[g];
    int kk = min(cnt, MAXP);
    if (lane < kk) toks[warp][lane] = g_slots[g*MAXP + lane];
    __syncwarp();

    int h = lane >> 2;
    float m = gS[g*NH + h];
    for (int tkn = 0; tkn < kk; tkn++) {
        int p = toks[warp][tkn];
        m = fmaxf(m, Ssc[p*NH + h]);
    }
    float e = expf(gS[g*NH + h] - m);
    float sum = e;
    float4 gv = *(const float4*)(gV + (size_t)g*E + lane*4);
    float4 acc = make_float4(e*gv.x, e*gv.y, e*gv.z, e*gv.w);
    for (int tkn = 0; tkn < kk; tkn++) {
        int p = toks[warp][tkn];
        float w = expf(Ssc[p*NH + h] - m);
        sum += w;
        float4 v = *(const float4*)(V + (size_t)p*E + lane*4);
        acc.x += w*v.x; acc.y += w*v.y; acc.z += w*v.z; acc.w += w*v.w;
    }
    float inv = 1.0f / sum;
    float4 o = make_float4(acc.x*inv, acc.y*inv, acc.z*inv, acc.w*inv);
    *(float4*)(out + (size_t)g*E + lane*4) = o;
}

// ---------------- launch ----------------
extern "C" void kernel_launch(void* const* d_in, const int* in_sizes, int n_in,
                              void* d_out, int out_size) {
    const float* x      = (const float*)d_in[0];
    const float* z      = (const float*)d_in[1];
    const float* x_grid = (const float*)d_in[2];
    const float* z_grid = (const float*)d_in[3];
    const float* latent = (const float*)d_in[4];
    const float* Wq     = (const float*)d_in[5];
    const float* Wk     = (const float*)d_in[6];
    const float* Wv     = (const float*)d_in[7];
    const float* Wo     = (const float*)d_in[8];

    float* out = (float*)d_out;
    float* zg_out = out;
    const int XG_ELEMS = NB*SG*2;
    if (out_size == NCELL*E + XG_ELEMS) {
        cudaMemcpyAsync(out, x_grid, (size_t)XG_ELEMS*sizeof(float),
                        cudaMemcpyDeviceToDevice);
        zg_out = out + XG_ELEMS;
    }

    void *pV, *pS, *pAO, *pWv, *pWo;
    cudaGetSymbolAddress(&pV,  g_V);
    cudaGetSymbolAddress(&pS,  g_score);
    cudaGetSymbolAddress(&pAO, g_attout);
    cudaGetSymbolAddress(&pWv, g_WvSp);
    cudaGetSymbolAddress(&pWo, g_WoSp);

    cudaFuncSetAttribute(gemm_tc<true>,  cudaFuncAttributeMaxDynamicSharedMemorySize, GEMM_SMEM);
    cudaFuncSetAttribute(gemm_tc<false>, cudaFuncAttributeMaxDynamicSharedMemorySize, GEMM_SMEM);

    zero_kernel<<<(NCELL+255)/256, 256>>>();
    prep_w<<<128, 128>>>(Wv, (__nv_bfloat16*)pWv);
    prep_w<<<128, 128>>>(Wo, (__nv_bfloat16*)pWo);
    prep_kernel<<<1, 128>>>(latent, Wq, Wk);
    scatter_kernel<<<(NPT+255)/256, 256>>>(x);

    gemm_tc<true><<<NROWS/64, 256, GEMM_SMEM>>>(z, z_grid, NPT/64,
                                                (const __nv_bfloat16*)pWv, 272*SK*2,
                                                (float*)pV, (float*)pS);
    attn_kernel<<<NCELL/8, 256>>>();

    gemm_tc<false><<<NCELL/64, 256, GEMM_SMEM>>>((const float*)pAO, (const float*)pAO,
                                                 NCELL/64,
                                                 (const __nv_bfloat16*)pWo, 256*SK*2,
                                                 zg_out, nullptr);
}

// round 8
// speedup vs baseline: 3.0024x; 1.1667x over previous
#include <cuda_runtime.h>
#include <cuda_bf16.h>
#include <cstdint>

#define NB    8
#define NPTS  8192
#define E     128
#define HG    64
#define WG    64
#define SG    (HG*WG)          // 4096
#define NCELL (NB*SG)          // 32768
#define NPT   (NB*NPTS)        // 65536
#define NROWS (NPT+NCELL)      // 98304
#define MAXP  20
#define NH    8

#define SK 136                 // padded k-stride (bf16 elements)

// ---------------- scratch ----------------
__device__ int   g_count[NCELL];
__device__ int   g_slots[NCELL*MAXP];
__device__ float g_q[E];
__device__ float g_score[(size_t)NROWS*NH];    // point scores then grid scores
__device__ float g_V[(size_t)NROWS*E];         // z@Wv then z_grid@Wv
__device__ float g_attout[(size_t)NCELL*E];
// pre-split weights: [Whi 128xSK][Wlo 128xSK][ATh 8xSK][ATl 8xSK]
__device__ __align__(16) __nv_bfloat16 g_WvSp[272*SK];
__device__ __align__(16) __nv_bfloat16 g_WoSp[256*SK];

// ---------------- mma / ldmatrix helpers ----------------
__device__ __forceinline__ void mma16816(float* c, const uint32_t* a, uint32_t b0, uint32_t b1) {
    asm volatile(
        "mma.sync.aligned.m16n8k16.row.col.f32.bf16.bf16.f32 "
        "{%0,%1,%2,%3}, {%4,%5,%6,%7}, {%8,%9}, {%0,%1,%2,%3};"
        : "+f"(c[0]), "+f"(c[1]), "+f"(c[2]), "+f"(c[3])
        : "r"(a[0]), "r"(a[1]), "r"(a[2]), "r"(a[3]), "r"(b0), "r"(b1));
}
__device__ __forceinline__ void ldsm_x4(uint32_t* r, uint32_t a) {
    asm volatile("ldmatrix.sync.aligned.m8n8.x4.shared.b16 {%0,%1,%2,%3}, [%4];"
        : "=r"(r[0]), "=r"(r[1]), "=r"(r[2]), "=r"(r[3]) : "r"(a));
}
__device__ __forceinline__ void ldsm_x2(uint32_t* r, uint32_t a) {
    asm volatile("ldmatrix.sync.aligned.m8n8.x2.shared.b16 {%0,%1}, [%2];"
        : "=r"(r[0]), "=r"(r[1]) : "r"(a));
}
__device__ __forceinline__ uint32_t pack_hi(float x, float y) {
    __nv_bfloat162 h = __halves2bfloat162(__float2bfloat16(x), __float2bfloat16(y));
    return *(uint32_t*)&h;
}
__device__ __forceinline__ uint32_t pack_lo(float x, float y) {
    __nv_bfloat16 hx = __float2bfloat16(x), hy = __float2bfloat16(y);
    __nv_bfloat162 l = __halves2bfloat162(__float2bfloat16(x - __bfloat162float(hx)),
                                          __float2bfloat16(y - __bfloat162float(hy)));
    return *(uint32_t*)&l;
}
__device__ __forceinline__ void cp_async16(uint32_t dst, const void* src) {
    asm volatile("cp.async.cg.shared.global [%0], [%1], 16;" :: "r"(dst), "l"(src));
}

// ---------------- fused GEMM (+ optional score) ----------------
// 64x128 tile, 256 thr = 8 warps (2m x 4n); each warp 32x32 = 2x4 m16n8 tiles.
// bf16 hi/lo split, 3 accumulating passes. 2 CTAs/SM.
#define SM_AHI 0
#define SM_ALO (64*SK)
#define SM_BHI (128*SK)
#define SM_BLO (256*SK)
#define SM_SBH (384*SK)
#define SM_SBL (392*SK)
#define GEMM_SMEM (400*SK*2)     // 108800 B

template<bool DO_SCORE>
__global__ void __launch_bounds__(256, 2) gemm_tc(const float* __restrict__ Z1,
                                                  const float* __restrict__ Z2, int nb1,
                                                  const __nv_bfloat16* __restrict__ Wsp,
                                                  int wbytes,
                                                  float* __restrict__ C,
                                                  float* __restrict__ Sout) {
    extern __shared__ __nv_bfloat16 sm[];
    const int t    = threadIdx.x;
    const int wid  = t >> 5;
    const int lane = t & 31;
    const int gRow0 = blockIdx.x * 64;
    const float* src;
    int m0;
    if ((int)blockIdx.x < nb1) { src = Z1; m0 = gRow0; }
    else                       { src = Z2; m0 = (blockIdx.x - nb1) * 64; }

    const uint32_t sb = (uint32_t)__cvta_generic_to_shared(sm);

    // ---- B (+score) staging: linear cp.async copy of pre-split blob ----
    {
        const char* gsrc = (const char*)Wsp;
        uint32_t bdst = sb + SM_BHI*2;
        for (int off = t*16; off < wbytes; off += 256*16)
            cp_async16(bdst + off, gsrc + off);
        asm volatile("cp.async.commit_group;");
    }

    // ---- A staging: each thread one quarter-row (32 floats), split hi/lo ----
    {
        int row = t >> 2;
        int kq  = (t & 3) << 5;
        const float4* zr = (const float4*)(src + (size_t)(m0 + row) * E + kq);
        __nv_bfloat16* ah = sm + SM_AHI + row*SK + kq;
        __nv_bfloat16* al = sm + SM_ALO + row*SK + kq;
        #pragma unroll
        for (int i = 0; i < 8; i++) {
            float4 v = zr[i];
            ((uint32_t*)(ah + i*4))[0] = pack_hi(v.x, v.y);
            ((uint32_t*)(ah + i*4))[1] = pack_hi(v.z, v.w);
            ((uint32_t*)(al + i*4))[0] = pack_lo(v.x, v.y);
            ((uint32_t*)(al + i*4))[1] = pack_lo(v.z, v.w);
        }
    }
    asm volatile("cp.async.wait_group 0;" ::: "memory");
    __syncthreads();

    const int mw = wid >> 2;            // 0..1 : rows mw*32
    const int nw = wid & 3;             // 0..3 : cols nw*32
    const int g  = lane >> 2;
    const int tg = lane & 3;

    // per-lane ldmatrix addresses (byte offsets)
    uint32_t aAh[2], aAl[2];
    #pragma unroll
    for (int mt = 0; mt < 2; mt++) {
        int row = mw*32 + mt*16 + (lane & 15);
        int col = (lane >> 4) << 3;
        aAh[mt] = sb + (SM_AHI + row*SK + col) * 2;
        aAl[mt] = sb + (SM_ALO + row*SK + col) * 2;
    }
    uint32_t aBh[2], aBl[2];
    #pragma unroll
    for (int c = 0; c < 2; c++) {
        int row = nw*32 + c*16 + (lane & 7) + ((lane >> 4) << 3);
        int col = ((lane >> 3) & 1) << 3;
        aBh[c] = sb + (SM_BHI + row*SK + col) * 2;
        aBl[c] = sb + (SM_BLO + row*SK + col) * 2;
    }
    uint32_t aSh = 0, aSl = 0;
    if (DO_SCORE) {
        int row = lane & 7;
        int col = ((lane >> 3) & 1) << 3;
        aSh = sb + (SM_SBH + row*SK + col) * 2;
        aSl = sb + (SM_SBL + row*SK + col) * 2;
    }

    float acc[2][4][4];
    #pragma unroll
    for (int a = 0; a < 2; a++)
        #pragma unroll
        for (int b = 0; b < 4; b++)
            #pragma unroll
            for (int c = 0; c < 4; c++) acc[a][b][c] = 0.f;
    float sacc[2][4] = {{0.f,0.f,0.f,0.f},{0.f,0.f,0.f,0.f}};

    #pragma unroll
    for (int ks = 0; ks < 8; ks++) {
        const uint32_t ko = ks * 32;
        uint32_t ah[2][4], al[2][4];
        ldsm_x4(ah[0], aAh[0] + ko);
        ldsm_x4(ah[1], aAh[1] + ko);
        ldsm_x4(al[0], aAl[0] + ko);
        ldsm_x4(al[1], aAl[1] + ko);

        if (DO_SCORE && nw == 0) {
            uint32_t sh[2], sl[2];
            ldsm_x2(sh, aSh + ko);
            ldsm_x2(sl, aSl + ko);
            #pragma unroll
            for (int mt = 0; mt < 2; mt++) {
                mma16816(sacc[mt], ah[mt], sh[0], sh[1]);
                mma16816(sacc[mt], al[mt], sh[0], sh[1]);
                mma16816(sacc[mt], ah[mt], sl[0], sl[1]);
            }
        }
        #pragma unroll
        for (int c = 0; c < 2; c++) {
            uint32_t bh[4], bl[4];
            ldsm_x4(bh, aBh[c] + ko);
            ldsm_x4(bl, aBl[c] + ko);
            #pragma unroll
            for (int mt = 0; mt < 2; mt++) {
                mma16816(acc[mt][2*c+0], ah[mt], bh[0], bh[1]);
                mma16816(acc[mt][2*c+1], ah[mt], bh[2], bh[3]);
                mma16816(acc[mt][2*c+0], al[mt], bh[0], bh[1]);
                mma16816(acc[mt][2*c+1], al[mt], bh[2], bh[3]);
                mma16816(acc[mt][2*c+0], ah[mt], bl[0], bl[1]);
                mma16816(acc[mt][2*c+1], ah[mt], bl[2], bl[3]);
            }
        }
    }

    // ---- epilogue ----
    #pragma unroll
    for (int mt = 0; mt < 2; mt++) {
        int row = gRow0 + mw*32 + mt*16 + g;
        #pragma unroll
        for (int nt = 0; nt < 4; nt++) {
            int col = nw*32 + nt*8 + tg*2;
            *(float2*)(C + (size_t)row * E + col) =
                make_float2(acc[mt][nt][0], acc[mt][nt][1]);
            *(float2*)(C + (size_t)(row + 8) * E + col) =
                make_float2(acc[mt][nt][2], acc[mt][nt][3]);
        }
    }
    if (DO_SCORE && nw == 0) {
        #pragma unroll
        for (int mt = 0; mt < 2; mt++) {
            int row = gRow0 + mw*32 + mt*16 + g;
            *(float2*)(Sout + (size_t)row * NH + tg*2) =
                make_float2(sacc[mt][0], sacc[mt][1]);
            *(float2*)(Sout + (size_t)(row + 8) * NH + tg*2) =
                make_float2(sacc[mt][2], sacc[mt][3]);
        }
    }
}

// ---------------- prep kernels ----------------
// split + transpose W -> dst = [hi 128xSK][lo 128xSK] (dst[n][k] = W[k][n])
__global__ void prep_w(const float* __restrict__ W, __nv_bfloat16* __restrict__ dst) {
    int n = blockIdx.x;     // 128
    int k = threadIdx.x;    // 128
    float v = W[(size_t)k*E + n];
    __nv_bfloat16 h = __float2bfloat16(v);
    dst[n*SK + k] = h;
    dst[128*SK + n*SK + k] = __float2bfloat16(v - __bfloat162float(h));
}

// q = latent @ Wq : 1 block x 1024 threads, d-dim split over 8 groups + smem reduce
__global__ void prep_q(const float* __restrict__ latent, const float* __restrict__ Wq) {
    __shared__ float lat[E];
    __shared__ float part[8][E];
    int t  = threadIdx.x & 127;
    int dd = threadIdx.x >> 7;       // 0..7
    if (threadIdx.x < E) lat[t] = latent[t];
    __syncthreads();
    float a = 0.f;
    #pragma unroll
    for (int i = 0; i < 16; i++) {
        int d = dd*16 + i;
        a += lat[d] * Wq[d*E + t];
    }
    part[dd][t] = a;
    __syncthreads();
    if (threadIdx.x < E) {
        float s = 0.f;
        #pragma unroll
        for (int i = 0; i < 8; i++) s += part[i][t];
        g_q[t] = s;
    }
}

// AT[h][k] = 0.25 * sum_i Wk[k][16h+i] * q[16h+i] -> split into g_WvSp tail
__global__ void prep_at(const float* __restrict__ Wk) {
    __shared__ float qs[E];
    if (threadIdx.x < E) qs[threadIdx.x] = g_q[threadIdx.x];
    __syncthreads();
    int id = blockIdx.x * 128 + threadIdx.x;   // 0..1023
    int k = id >> 3, h = id & 7;
    float s = 0.f;
    #pragma unroll
    for (int i = 0; i < 16; i++) s += Wk[(size_t)k*E + h*16 + i] * qs[h*16 + i];
    s *= 0.25f;
    __nv_bfloat16 hi = __float2bfloat16(s);
    g_WvSp[256*SK + h*SK + k] = hi;
    g_WvSp[264*SK + h*SK + k] = __float2bfloat16(s - __bfloat162float(hi));
}

__global__ void zero_kernel() {
    int i = blockIdx.x * blockDim.x + threadIdx.x;
    if (i < NCELL) g_count[i] = 0;
}

__global__ void scatter_kernel(const float* __restrict__ x) {
    int p = blockIdx.x * blockDim.x + threadIdx.x;
    if (p >= NPT) return;
    int b = p >> 13;
    float x0 = x[2*p], x1 = x[2*p+1];
    int i0 = (int)rintf(x0 * 63.0f); i0 = min(max(i0, 0), 63);
    int i1 = (int)rintf(x1 * 63.0f); i1 = min(max(i1, 0), 63);
    int cell = b*SG + i0*WG + i1;
    int slot = atomicAdd(&g_count[cell], 1);
    if (slot < MAXP) g_slots[cell*MAXP + slot] = p;
}

__global__ void attn_kernel() {
    const float* V   = g_V;
    const float* gV  = g_V + (size_t)NPT*E;
    const float* Ssc = g_score;
    const float* gS  = g_score + (size_t)NPT*NH;
    float* out = g_attout;

    __shared__ int toks[8][MAXP];
    int warp = threadIdx.x >> 5, lane = threadIdx.x & 31;
    int g = blockIdx.x*8 + warp;
    int cnt = g_count[g];
    int kk = min(cnt, MAXP);
    if (lane < kk) toks[warp][lane] = g_slots[g*MAXP + lane];
    __syncwarp();

    int h = lane >> 2;
    float m = gS[g*NH + h];
    for (int tkn = 0; tkn < kk; tkn++) {
        int p = toks[warp][tkn];
        m = fmaxf(m, Ssc[p*NH + h]);
    }
    float e = expf(gS[g*NH + h] - m);
    float sum = e;
    float4 gv = *(const float4*)(gV + (size_t)g*E + lane*4);
    float4 acc = make_float4(e*gv.x, e*gv.y, e*gv.z, e*gv.w);
    for (int tkn = 0; tkn < kk; tkn++) {
        int p = toks[warp][tkn];
        float w = expf(Ssc[p*NH + h] - m);
        sum += w;
        float4 v = *(const float4*)(V + (size_t)p*E + lane*4);
        acc.x += w*v.x; acc.y += w*v.y; acc.z += w*v.z; acc.w += w*v.w;
    }
    float inv = 1.0f / sum;
    float4 o = make_float4(acc.x*inv, acc.y*inv, acc.z*inv, acc.w*inv);
    *(float4*)(out + (size_t)g*E + lane*4) = o;
}

// ---------------- launch ----------------
extern "C" void kernel_launch(void* const* d_in, const int* in_sizes, int n_in,
                              void* d_out, int out_size) {
    const float* x      = (const float*)d_in[0];
    const float* z      = (const float*)d_in[1];
    const float* x_grid = (const float*)d_in[2];
    const float* z_grid = (const float*)d_in[3];
    const float* latent = (const float*)d_in[4];
    const float* Wq     = (const float*)d_in[5];
    const float* Wk     = (const float*)d_in[6];
    const float* Wv     = (const float*)d_in[7];
    const float* Wo     = (const float*)d_in[8];

    float* out = (float*)d_out;
    float* zg_out = out;
    const int XG_ELEMS = NB*SG*2;
    if (out_size == NCELL*E + XG_ELEMS) {
        cudaMemcpyAsync(out, x_grid, (size_t)XG_ELEMS*sizeof(float),
                        cudaMemcpyDeviceToDevice);
        zg_out = out + XG_ELEMS;
    }

    void *pV, *pS, *pAO, *pWv, *pWo;
    cudaGetSymbolAddress(&pV,  g_V);
    cudaGetSymbolAddress(&pS,  g_score);
    cudaGetSymbolAddress(&pAO, g_attout);
    cudaGetSymbolAddress(&pWv, g_WvSp);
    cudaGetSymbolAddress(&pWo, g_WoSp);

    cudaFuncSetAttribute(gemm_tc<true>,  cudaFuncAttributeMaxDynamicSharedMemorySize, GEMM_SMEM);
    cudaFuncSetAttribute(gemm_tc<false>, cudaFuncAttributeMaxDynamicSharedMemorySize, GEMM_SMEM);

    zero_kernel<<<(NCELL+255)/256, 256>>>();
    prep_w<<<128, 128>>>(Wv, (__nv_bfloat16*)pWv);
    prep_w<<<128, 128>>>(Wo, (__nv_bfloat16*)pWo);
    prep_q<<<1, 1024>>>(latent, Wq);
    prep_at<<<8, 128>>>(Wk);
    scatter_kernel<<<(NPT+255)/256, 256>>>(x);

    gemm_tc<true><<<NROWS/64, 256, GEMM_SMEM>>>(z, z_grid, NPT/64,
                                                (const __nv_bfloat16*)pWv, 272*SK*2,
                                                (float*)pV, (float*)pS);
    attn_kernel<<<NCELL/8, 256>>>();

    gemm_tc<false><<<NCELL/64, 256, GEMM_SMEM>>>((const float*)pAO, (const float*)pAO,
                                                 NCELL/64,
                                                 (const __nv_bfloat16*)pWo, 256*SK*2,
                                                 zg_out, nullptr);
}